// round 11
// baseline (speedup 1.0000x reference)
#include <cuda_runtime.h>

#define NV 1497600          // 256 * 5850
#define NE 4492800          // 3 * NV
#define NB 256
#define VPM 5850
#define KDIM 58500          // VPM * 10
#define NEG 0.01f

// ---------------- scratch (static device memory; no allocs) ----------------
__device__ float g_p4[(size_t)NV * 4];    // (vx, vy, vz, 1)
__device__ float g_s1[(size_t)NV * 4];    // pass-1 scatter acc (w = degree)
__device__ float g_q4[(size_t)NV * 4];    // leaky(xA)[0..3]
__device__ float g_q1[(size_t)NV];        // leaky(xA)[4]
__device__ float g_s24[(size_t)NV * 4];   // pass-2 scatter acc [0..3]
__device__ float g_s21[(size_t)NV];       // pass-2 scatter acc [4]
__device__ float g_degf[(size_t)NV];      // dense degree copy
__device__ float g_y [(size_t)NV * 10];   // fc1 output == flat (256, 58500)
__device__ float g_logits[NB * 64];

__device__ __forceinline__ float leaky(float t) { return t >= 0.f ? t : NEG * t; }

__device__ __forceinline__ void red4(float* p, float4 v) {
    asm volatile("red.global.add.v4.f32 [%0], {%1,%2,%3,%4};"
                 :: "l"(p), "f"(v.x), "f"(v.y), "f"(v.z), "f"(v.w) : "memory");
}
__device__ __forceinline__ void red1(float* p, float v) {
    asm volatile("red.global.add.f32 [%0], %1;" :: "l"(p), "f"(v) : "memory");
}

// ---------------- K1: pack verts -> p4, zero s1 + logits ----------------
__global__ void k1_pack(const float* __restrict__ verts) {
    int v = blockIdx.x * blockDim.x + threadIdx.x;
    if (v >= NV) return;
    float p0 = verts[(size_t)v*3+0], p1 = verts[(size_t)v*3+1], p2 = verts[(size_t)v*3+2];
    *(float4*)&g_p4[(size_t)v*4] = make_float4(p0, p1, p2, 1.0f);
    *(float4*)&g_s1[(size_t)v*4] = make_float4(0.f, 0.f, 0.f, 0.f);
    if (v < NB * 64) g_logits[v] = 0.f;
}

// ---------------- K2: pass-1 scatter (raw verts + degree) ----------------
__global__ void k2_scatter1(const int* __restrict__ edges) {
    int e = blockIdx.x * blockDim.x + threadIdx.x;
    if (e >= NE) return;
    int2 ij = __ldcs(&((const int2*)edges)[e]);
    float4 a = *(const float4*)&g_p4[(size_t)ij.y * 4];
    float4 b = *(const float4*)&g_p4[(size_t)ij.x * 4];
    red4(&g_s1[(size_t)ij.x * 4], a);
    red4(&g_s1[(size_t)ij.y * 4], b);
}

// ---- K3: xA = leaky(p@w0a + b0a + s1.xyz@w1a + deg*b1a) -> q4/q1; zero s2 ----
__global__ void k3_lin_a(const float* __restrict__ w0, const float* __restrict__ b0,
                         const float* __restrict__ w1, const float* __restrict__ b1) {
    __shared__ float sw0[15], sw1[15], sb0[5], sb1[5];
    int t = threadIdx.x;
    if (t < 15) { sw0[t] = w0[t]; sw1[t] = w1[t]; }
    if (t < 5)  { sb0[t] = b0[t]; sb1[t] = b1[t]; }
    __syncthreads();
    int v = blockIdx.x * blockDim.x + t;
    if (v >= NV) return;
    float4 p = *(const float4*)&g_p4[(size_t)v*4];
    float4 s = *(const float4*)&g_s1[(size_t)v*4];
    float x[5];
#pragma unroll
    for (int c = 0; c < 5; c++) {
        float a = fmaf(sw0[c*3+0], p.x, fmaf(sw0[c*3+1], p.y, fmaf(sw0[c*3+2], p.z, sb0[c])));
        a = fmaf(sw1[c*3+0], s.x, fmaf(sw1[c*3+1], s.y, fmaf(sw1[c*3+2], s.z, a)));
        a = fmaf(s.w, sb1[c], a);
        x[c] = leaky(a);
    }
    *(float4*)&g_q4[(size_t)v*4] = make_float4(x[0], x[1], x[2], x[3]);
    g_q1[v] = x[4];
    g_degf[v] = s.w;
    *(float4*)&g_s24[(size_t)v*4] = make_float4(0.f, 0.f, 0.f, 0.f);
    g_s21[v] = 0.f;
}

// ---------------- K4: pass-2 scatter (5-float leaky(xA)) ----------------
__global__ void k4_scatter2(const int* __restrict__ edges) {
    int e = blockIdx.x * blockDim.x + threadIdx.x;
    if (e >= NE) return;
    int2 ij = __ldcs(&((const int2*)edges)[e]);
    float4 a  = *(const float4*)&g_q4[(size_t)ij.y * 4];
    float  a4 = g_q1[ij.y];
    float4 b  = *(const float4*)&g_q4[(size_t)ij.x * 4];
    float  b4 = g_q1[ij.x];
    red4(&g_s24[(size_t)ij.x * 4], a);  red1(&g_s21[ij.x], a4);
    red4(&g_s24[(size_t)ij.y * 4], b);  red1(&g_s21[ij.y], b4);
}

// ---- K5: xB = leaky(x@w0b + b0b + s2@w1b + deg*b1b); y = leaky(xB@fc1 + fc1b) ----
__global__ void k5_fused(const float* __restrict__ w0, const float* __restrict__ b0,
                         const float* __restrict__ w1, const float* __restrict__ b1,
                         const float* __restrict__ fw, const float* __restrict__ fb) {
    __shared__ float sw0[100], sw1[100], sb0[20], sb1[20], sfw[200], sfb[10];
    int t = threadIdx.x;
    if (t < 100) { sw0[t] = w0[t]; sw1[t] = w1[t]; }
    if (t < 20)  { sb0[t] = b0[t]; sb1[t] = b1[t]; }
    if (t < 200) sfw[t] = fw[t];
    if (t < 10)  sfb[t] = fb[t];
    __syncthreads();
    int v = blockIdx.x * blockDim.x + t;
    if (v >= NV) return;
    float4 xq = *(const float4*)&g_q4[(size_t)v*4];
    float  x4 = g_q1[v];
    float4 sq = *(const float4*)&g_s24[(size_t)v*4];
    float  s4 = g_s21[v];
    float  deg = g_degf[v];
    float x[5] = {xq.x, xq.y, xq.z, xq.w, x4};
    float s[5] = {sq.x, sq.y, sq.z, sq.w, s4};
    float xb[20];
#pragma unroll
    for (int n = 0; n < 20; n++) {
        float a = fmaf(deg, sb1[n], sb0[n]);
#pragma unroll
        for (int c = 0; c < 5; c++) {
            a = fmaf(x[c], sw0[n*5 + c], a);
            a = fmaf(s[c], sw1[n*5 + c], a);
        }
        xb[n] = leaky(a);
    }
    float h[10];
#pragma unroll
    for (int n = 0; n < 10; n++) {
        float a = sfb[n];
#pragma unroll
        for (int c = 0; c < 20; c++) a = fmaf(xb[c], sfw[n*20 + c], a);
        h[n] = leaky(a);
    }
#pragma unroll
    for (int n = 0; n < 10; n += 2)
        *(float2*)&g_y[(size_t)v*10 + n] = make_float2(h[n], h[n+1]);
}

// ------- K6: split-K GEMM, BM=256 (whole M), BN=64, 8x8 thread tiles -------
#define K6_BK 16
#define K6_KSPLIT 128
__global__ void __launch_bounds__(256, 2)
k6_gemm(const float* __restrict__ w) {
    __shared__ float Ys[256][K6_BK + 1];
    __shared__ float Ws[64][K6_BK + 1];
    int t = threadIdx.x;                  // 256 threads
    int kbase = blockIdx.x * K6_KSPLIT;
    int tr = t & 31;                      // lane: m sub-index
    int tc = t >> 5;                      // warp: n group (8 consecutive cols)
    float acc[8][8] = {};
    for (int kk = 0; kk < K6_KSPLIT; kk += K6_BK) {
        // load Y tile: 256 rows x 16 k = 1024 float4; 4 per thread
#pragma unroll
        for (int r = 0; r < 4; r++) {
            int idx = t + r * 256;
            int row = idx >> 2;
            int kc  = (idx & 3) * 4;
            int kg  = kbase + kk + kc;
            float4 yv = make_float4(0.f, 0.f, 0.f, 0.f);
            if (kg < KDIM) yv = __ldcs((const float4*)&g_y[(size_t)row * KDIM + kg]);
            Ys[row][kc+0] = yv.x; Ys[row][kc+1] = yv.y;
            Ys[row][kc+2] = yv.z; Ys[row][kc+3] = yv.w;
        }
        // load W tile: 64 rows x 16 k = 256 float4; 1 per thread
        {
            int row = t >> 2;
            int kc  = (t & 3) * 4;
            int kg  = kbase + kk + kc;
            float4 wv = make_float4(0.f, 0.f, 0.f, 0.f);
            if (kg < KDIM) wv = __ldcs((const float4*)&w[(size_t)row * KDIM + kg]);
            Ws[row][kc+0] = wv.x; Ws[row][kc+1] = wv.y;
            Ws[row][kc+2] = wv.z; Ws[row][kc+3] = wv.w;
        }
        __syncthreads();
#pragma unroll
        for (int k2 = 0; k2 < K6_BK; k2++) {
            float ya[8], wa[8];
#pragma unroll
            for (int u = 0; u < 8; u++) ya[u] = Ys[tr + 32*u][k2];
#pragma unroll
            for (int v = 0; v < 8; v++) wa[v] = Ws[tc*8 + v][k2];
#pragma unroll
            for (int u = 0; u < 8; u++)
#pragma unroll
                for (int v = 0; v < 8; v++)
                    acc[u][v] = fmaf(ya[u], wa[v], acc[u][v]);
        }
        __syncthreads();
    }
#pragma unroll
    for (int u = 0; u < 8; u++) {
        int row = tr + 32*u;
        red4(&g_logits[row*64 + tc*8    ], make_float4(acc[u][0], acc[u][1], acc[u][2], acc[u][3]));
        red4(&g_logits[row*64 + tc*8 + 4], make_float4(acc[u][4], acc[u][5], acc[u][6], acc[u][7]));
    }
}

// ---------------- K7: bias + softmax(64) ----------------
__global__ void k7_softmax(const float* __restrict__ fb, float* __restrict__ out) {
    int b = blockIdx.x;
    int t = threadIdx.x;   // 64 threads
    float v = g_logits[b * 64 + t] + fb[t];
    __shared__ float r0[2], r1[2];
    float m = v;
#pragma unroll
    for (int o = 16; o; o >>= 1) m = fmaxf(m, __shfl_xor_sync(0xffffffffu, m, o));
    if ((t & 31) == 0) r0[t >> 5] = m;
    __syncthreads();
    m = fmaxf(r0[0], r0[1]);
    float e = expf(v - m);
    float s = e;
#pragma unroll
    for (int o = 16; o; o >>= 1) s += __shfl_xor_sync(0xffffffffu, s, o);
    if ((t & 31) == 0) r1[t >> 5] = s;
    __syncthreads();
    s = r1[0] + r1[1];
    out[b * 64 + t] = e / s;
}

// ---------------- launch ----------------
extern "C" void kernel_launch(void* const* d_in, const int* in_sizes, int n_in,
                              void* d_out, int out_size) {
    const float* verts = (const float*)d_in[0];
    const int*   edges = (const int*)  d_in[1];
    const float* w0a = (const float*)d_in[2];  const float* b0a = (const float*)d_in[3];
    const float* w1a = (const float*)d_in[4];  const float* b1a = (const float*)d_in[5];
    const float* w0b = (const float*)d_in[6];  const float* b0b = (const float*)d_in[7];
    const float* w1b = (const float*)d_in[8];  const float* b1b = (const float*)d_in[9];
    const float* f1w = (const float*)d_in[10]; const float* f1b = (const float*)d_in[11];
    const float* f2w = (const float*)d_in[12]; const float* f2b = (const float*)d_in[13];
    float* out = (float*)d_out;

    k1_pack    <<<(NV + 255) / 256, 256>>>(verts);
    k2_scatter1<<<(NE + 255) / 256, 256>>>(edges);
    k3_lin_a   <<<(NV + 255) / 256, 256>>>(w0a, b0a, w1a, b1a);
    k4_scatter2<<<(NE + 255) / 256, 256>>>(edges);
    k5_fused   <<<(NV + 255) / 256, 256>>>(w0b, b0b, w1b, b1b, f1w, f1b);
    k6_gemm    <<<(KDIM + K6_KSPLIT - 1) / K6_KSPLIT, 256>>>(f2w);
    k7_softmax <<<NB, 64>>>(f2b, out);
}

// round 12
// speedup vs baseline: 1.0107x; 1.0107x over previous
#include <cuda_runtime.h>

#define NV 1497600          // 256 * 5850
#define NE 4492800          // 3 * NV
#define NB 256
#define VPM 5850
#define KDIM 58500          // VPM * 10
#define NEG 0.01f

// ---------------- scratch (static device memory; no allocs) ----------------
__device__ float g_p4[(size_t)NV * 4];    // (vx, vy, vz, 1)
__device__ float g_s1[(size_t)NV * 4];    // pass-1 scatter acc (w = degree)
__device__ float g_q8[(size_t)NV * 8];    // leaky(xA), 5 used, stride 8 (32B sector)
__device__ float g_s28[(size_t)NV * 8];   // pass-2 scatter acc, stride 8
__device__ float g_degf[(size_t)NV];      // dense degree copy
__device__ float g_y [(size_t)NV * 10];   // fc1 output == flat (256, 58500)
__device__ float g_logits[NB * 64];

__device__ __forceinline__ float leaky(float t) { return t >= 0.f ? t : NEG * t; }

__device__ __forceinline__ void red4(float* p, float4 v) {
    asm volatile("red.global.add.v4.f32 [%0], {%1,%2,%3,%4};"
                 :: "l"(p), "f"(v.x), "f"(v.y), "f"(v.z), "f"(v.w) : "memory");
}
__device__ __forceinline__ void red1(float* p, float v) {
    asm volatile("red.global.add.f32 [%0], %1;" :: "l"(p), "f"(v) : "memory");
}

// ---------- packed f32x2 helpers (FFMA2 — only reachable via PTX) ----------
typedef unsigned long long ull;
__device__ __forceinline__ ull pk2(float lo, float hi) {
    ull r; asm("mov.b64 %0, {%1, %2};" : "=l"(r) : "f"(lo), "f"(hi)); return r;
}
__device__ __forceinline__ void upk2(ull v, float& lo, float& hi) {
    asm("mov.b64 {%0, %1}, %2;" : "=f"(lo), "=f"(hi) : "l"(v));
}
__device__ __forceinline__ ull ffma2(ull a, ull b, ull c) {
    ull d; asm("fma.rn.f32x2 %0, %1, %2, %3;" : "=l"(d) : "l"(a), "l"(b), "l"(c)); return d;
}

// ---------------- K1: pack verts -> p4, zero s1 + logits ----------------
__global__ void k1_pack(const float* __restrict__ verts) {
    int v = blockIdx.x * blockDim.x + threadIdx.x;
    if (v >= NV) return;
    float p0 = verts[(size_t)v*3+0], p1 = verts[(size_t)v*3+1], p2 = verts[(size_t)v*3+2];
    *(float4*)&g_p4[(size_t)v*4] = make_float4(p0, p1, p2, 1.0f);
    *(float4*)&g_s1[(size_t)v*4] = make_float4(0.f, 0.f, 0.f, 0.f);
    if (v < NB * 64) g_logits[v] = 0.f;
}

// ---------------- K2: pass-1 scatter (raw verts + degree) ----------------
__global__ void k2_scatter1(const int* __restrict__ edges) {
    int e = blockIdx.x * blockDim.x + threadIdx.x;
    if (e >= NE) return;
    int2 ij = __ldcs(&((const int2*)edges)[e]);
    float4 a = *(const float4*)&g_p4[(size_t)ij.y * 4];
    float4 b = *(const float4*)&g_p4[(size_t)ij.x * 4];
    red4(&g_s1[(size_t)ij.x * 4], a);
    red4(&g_s1[(size_t)ij.y * 4], b);
}

// ---- K3: xA = leaky(p@w0a + b0a + s1.xyz@w1a + deg*b1a) -> q8; zero s28 ----
__global__ void k3_lin_a(const float* __restrict__ w0, const float* __restrict__ b0,
                         const float* __restrict__ w1, const float* __restrict__ b1) {
    __shared__ float sw0[15], sw1[15], sb0[5], sb1[5];
    int t = threadIdx.x;
    if (t < 15) { sw0[t] = w0[t]; sw1[t] = w1[t]; }
    if (t < 5)  { sb0[t] = b0[t]; sb1[t] = b1[t]; }
    __syncthreads();
    int v = blockIdx.x * blockDim.x + t;
    if (v >= NV) return;
    float4 p = *(const float4*)&g_p4[(size_t)v*4];
    float4 s = *(const float4*)&g_s1[(size_t)v*4];
    float x[5];
#pragma unroll
    for (int c = 0; c < 5; c++) {
        float a = fmaf(sw0[c*3+0], p.x, fmaf(sw0[c*3+1], p.y, fmaf(sw0[c*3+2], p.z, sb0[c])));
        a = fmaf(sw1[c*3+0], s.x, fmaf(sw1[c*3+1], s.y, fmaf(sw1[c*3+2], s.z, a)));
        a = fmaf(s.w, sb1[c], a);
        x[c] = leaky(a);
    }
    *(float4*)&g_q8[(size_t)v*8]     = make_float4(x[0], x[1], x[2], x[3]);
    *(float4*)&g_q8[(size_t)v*8 + 4] = make_float4(x[4], 0.f, 0.f, 0.f);
    *(float4*)&g_s28[(size_t)v*8]     = make_float4(0.f, 0.f, 0.f, 0.f);
    *(float4*)&g_s28[(size_t)v*8 + 4] = make_float4(0.f, 0.f, 0.f, 0.f);
    g_degf[v] = s.w;
}

// ---------------- K4: pass-2 scatter (5 floats, one 32B sector/vertex) ------
__global__ void k4_scatter2(const int* __restrict__ edges) {
    int e = blockIdx.x * blockDim.x + threadIdx.x;
    if (e >= NE) return;
    int2 ij = __ldcs(&((const int2*)edges)[e]);
    size_t oi = (size_t)ij.x * 8, oj = (size_t)ij.y * 8;
    float4 a  = *(const float4*)&g_q8[oj];
    float  a4 = g_q8[oj + 4];
    float4 b  = *(const float4*)&g_q8[oi];
    float  b4 = g_q8[oi + 4];
    red4(&g_s28[oi], a);  red1(&g_s28[oi + 4], a4);
    red4(&g_s28[oj], b);  red1(&g_s28[oj + 4], b4);
}

// ---- K5 (FFMA2): xB = leaky(x@w0b + b0b + s2@w1b + deg*b1b); y = leaky(fc1) ----
__global__ void k5_fused(const float* __restrict__ w0, const float* __restrict__ b0,
                         const float* __restrict__ w1, const float* __restrict__ b1,
                         const float* __restrict__ fw, const float* __restrict__ fb) {
    // weights packed as n-pair float2 in 64-bit words
    __shared__ ull sw0p[50], sw1p[50];   // [c*10 + p], pair p = (2p, 2p+1) of 20 outputs
    __shared__ ull sfwp[100];            // [c*5 + p],  pair p of 10 outputs
    __shared__ ull sb0p[10], sb1p[10], sfbp[5];
    int t = threadIdx.x;
    if (t < 50) {
        int c = t / 10, p = t % 10;
        sw0p[t] = pk2(w0[(2*p)*5 + c], w0[(2*p+1)*5 + c]);
        sw1p[t] = pk2(w1[(2*p)*5 + c], w1[(2*p+1)*5 + c]);
    }
    if (t < 100) {
        int c = t / 5, p = t % 5;
        sfwp[t] = pk2(fw[(2*p)*20 + c], fw[(2*p+1)*20 + c]);
    }
    if (t < 10) { sb0p[t] = pk2(b0[2*t], b0[2*t+1]); sb1p[t] = pk2(b1[2*t], b1[2*t+1]); }
    if (t < 5)  { sfbp[t] = pk2(fb[2*t], fb[2*t+1]); }
    __syncthreads();
    int v = blockIdx.x * blockDim.x + t;
    if (v >= NV) return;
    float4 xq = *(const float4*)&g_q8[(size_t)v*8];
    float  x4 = g_q8[(size_t)v*8 + 4];
    float4 sq = *(const float4*)&g_s28[(size_t)v*8];
    float  s4 = g_s28[(size_t)v*8 + 4];
    float  deg = g_degf[v];
    float x[5] = {xq.x, xq.y, xq.z, xq.w, x4};
    float s[5] = {sq.x, sq.y, sq.z, sq.w, s4};

    ull degd = pk2(deg, deg);
    ull xbp[10];
#pragma unroll
    for (int p = 0; p < 10; p++) xbp[p] = ffma2(degd, sb1p[p], sb0p[p]);
#pragma unroll
    for (int c = 0; c < 5; c++) {
        ull xc = pk2(x[c], x[c]);
        ull sc = pk2(s[c], s[c]);
#pragma unroll
        for (int p = 0; p < 10; p++)
            xbp[p] = ffma2(xc, sw0p[c*10 + p], ffma2(sc, sw1p[c*10 + p], xbp[p]));
    }
    ull hp[5];
#pragma unroll
    for (int p = 0; p < 5; p++) hp[p] = sfbp[p];
#pragma unroll
    for (int c2 = 0; c2 < 10; c2++) {
        float lo, hi; upk2(xbp[c2], lo, hi);
        lo = leaky(lo); hi = leaky(hi);
        ull xa = pk2(lo, lo), xb_ = pk2(hi, hi);
#pragma unroll
        for (int p = 0; p < 5; p++)
            hp[p] = ffma2(xa, sfwp[(2*c2)*5 + p], ffma2(xb_, sfwp[(2*c2+1)*5 + p], hp[p]));
    }
#pragma unroll
    for (int p = 0; p < 5; p++) {
        float lo, hi; upk2(hp[p], lo, hi);
        *(float2*)&g_y[(size_t)v*10 + 2*p] = make_float2(leaky(lo), leaky(hi));
    }
}

// ------- K6: split-K GEMM with FFMA2. BM=256 (whole M), BN=64. ----------
// KDIM = 58500 = 117 * 500; KSPLIT=500, BK=20 — no bounds checks needed.
#define K6_BK 20
#define K6_KSPLIT 500
__global__ void __launch_bounds__(256, 1)
k6_gemm(const float* __restrict__ w) {
    __shared__ float Ys[256][K6_BK + 1];   // [m][k]
    __shared__ float Wsk[K6_BK][66];       // [k][n] -> n-pairs contiguous for 8B loads
    int t = threadIdx.x;                   // 256 threads
    int kbase = blockIdx.x * K6_KSPLIT;
    int tr = t & 31;                       // m sub-index (lane)
    int tc = t >> 5;                       // warp id: n block of 8
    ull acc[8][4] = {};                    // 8 m x 4 n-pairs, packed f32x2
    for (int kk = 0; kk < K6_KSPLIT; kk += K6_BK) {
        // Y tile: 256 rows x 20 k = 1280 float4, 5 per thread
#pragma unroll
        for (int r = 0; r < 5; r++) {
            int idx = t + r * 256;
            int row = idx / 5;
            int kc  = (idx % 5) * 4;
            float4 yv = __ldcs((const float4*)&g_y[(size_t)row * KDIM + kbase + kk + kc]);
            Ys[row][kc+0] = yv.x; Ys[row][kc+1] = yv.y;
            Ys[row][kc+2] = yv.z; Ys[row][kc+3] = yv.w;
        }
        // W tile: 64 rows x 20 k = 320 float4, transposed into [k][n]
#pragma unroll
        for (int r = 0; r < 2; r++) {
            int idx = t + r * 256;
            if (idx < 320) {
                int n  = idx / 5;
                int kc = (idx % 5) * 4;
                float4 wv = __ldcs((const float4*)&w[(size_t)n * KDIM + kbase + kk + kc]);
                Wsk[kc+0][n] = wv.x; Wsk[kc+1][n] = wv.y;
                Wsk[kc+2][n] = wv.z; Wsk[kc+3][n] = wv.w;
            }
        }
        __syncthreads();
#pragma unroll 5
        for (int k2 = 0; k2 < K6_BK; k2++) {
            ull ya2[8];
#pragma unroll
            for (int u = 0; u < 8; u++) {
                float y = Ys[tr + 32*u][k2];
                ya2[u] = pk2(y, y);
            }
            ull wv[4];
#pragma unroll
            for (int v2 = 0; v2 < 4; v2++)
                wv[v2] = *(const ull*)&Wsk[k2][tc*8 + 2*v2];   // warp-uniform broadcast
#pragma unroll
            for (int u = 0; u < 8; u++)
#pragma unroll
                for (int v2 = 0; v2 < 4; v2++)
                    acc[u][v2] = ffma2(ya2[u], wv[v2], acc[u][v2]);
        }
        __syncthreads();
    }
#pragma unroll
    for (int u = 0; u < 8; u++) {
        int row = tr + 32*u;
        float a, b, c, d;
        upk2(acc[u][0], a, b); upk2(acc[u][1], c, d);
        red4(&g_logits[row*64 + tc*8], make_float4(a, b, c, d));
        upk2(acc[u][2], a, b); upk2(acc[u][3], c, d);
        red4(&g_logits[row*64 + tc*8 + 4], make_float4(a, b, c, d));
    }
}

// ---------------- K7: bias + softmax(64) ----------------
__global__ void k7_softmax(const float* __restrict__ fb, float* __restrict__ out) {
    int b = blockIdx.x;
    int t = threadIdx.x;   // 64 threads
    float v = g_logits[b * 64 + t] + fb[t];
    __shared__ float r0[2], r1[2];
    float m = v;
#pragma unroll
    for (int o = 16; o; o >>= 1) m = fmaxf(m, __shfl_xor_sync(0xffffffffu, m, o));
    if ((t & 31) == 0) r0[t >> 5] = m;
    __syncthreads();
    m = fmaxf(r0[0], r0[1]);
    float e = expf(v - m);
    float s = e;
#pragma unroll
    for (int o = 16; o; o >>= 1) s += __shfl_xor_sync(0xffffffffu, s, o);
    if ((t & 31) == 0) r1[t >> 5] = s;
    __syncthreads();
    s = r1[0] + r1[1];
    out[b * 64 + t] = e / s;
}

// ---------------- launch ----------------
extern "C" void kernel_launch(void* const* d_in, const int* in_sizes, int n_in,
                              void* d_out, int out_size) {
    const float* verts = (const float*)d_in[0];
    const int*   edges = (const int*)  d_in[1];
    const float* w0a = (const float*)d_in[2];  const float* b0a = (const float*)d_in[3];
    const float* w1a = (const float*)d_in[4];  const float* b1a = (const float*)d_in[5];
    const float* w0b = (const float*)d_in[6];  const float* b0b = (const float*)d_in[7];
    const float* w1b = (const float*)d_in[8];  const float* b1b = (const float*)d_in[9];
    const float* f1w = (const float*)d_in[10]; const float* f1b = (const float*)d_in[11];
    const float* f2w = (const float*)d_in[12]; const float* f2b = (const float*)d_in[13];
    float* out = (float*)d_out;

    k1_pack    <<<(NV + 255) / 256, 256>>>(verts);
    k2_scatter1<<<(NE + 255) / 256, 256>>>(edges);
    k3_lin_a   <<<(NV + 255) / 256, 256>>>(w0a, b0a, w1a, b1a);
    k4_scatter2<<<(NE + 255) / 256, 256>>>(edges);
    k5_fused   <<<(NV + 255) / 256, 256>>>(w0b, b0b, w1b, b1b, f1w, f1b);
    k6_gemm    <<<KDIM / K6_KSPLIT, 256>>>(f2w);   // 117 blocks
    k7_softmax <<<NB, 64>>>(f2b, out);
}